// round 1
// baseline (speedup 1.0000x reference)
#include <cuda_runtime.h>
#include <cuda_bf16.h>
#include <math.h>

// Problem constants
#define BB 4
#define LL 1024
#define DD 1024
#define HH 16
#define DK 64
#define MTOT (BB * LL)          // 4096
#define NBL  (BB * LL)          // 4096

// ---------------- scratch (static device memory; no allocations) -------------
__device__ float g_Q[MTOT * DD];
__device__ float g_K[MTOT * DD];
__device__ float g_V[MTOT * DD];
__device__ float g_M[MTOT * DD];      // merged head outputs
__device__ float g_G[DD * DD];        // M^T M
__device__ float g_mean[DD];
__device__ float g_partial[DD];

// ---------------- GEMM: C[M,N] = A[M,K] @ W[N,K]^T + bias --------------------
// 128x128 block tile, 16 K-tile, 256 threads, 8x8 microtile.
#define BM 128
#define BN 128
#define BK 16
#define PAD 4   // smem row pad (float)

__global__ __launch_bounds__(256) void gemm_bias_nt(
    const float* __restrict__ A, const float* __restrict__ W,
    const float* __restrict__ bias, float* __restrict__ C,
    int M, int N, int K)
{
    __shared__ float As[BK][BM + PAD];
    __shared__ float Ws[BK][BN + PAD];

    const int tid = threadIdx.x;
    const int tm = tid / 16;        // 0..15
    const int tn = tid % 16;        // 0..15
    const int by = blockIdx.y;      // M tile
    const int bx = blockIdx.x;      // N tile

    const float* Ablk = A + (size_t)by * BM * K;
    const float* Wblk = W + (size_t)bx * BN * K;

    float acc[8][8];
#pragma unroll
    for (int i = 0; i < 8; i++)
#pragma unroll
        for (int j = 0; j < 8; j++) acc[i][j] = 0.0f;

    for (int k0 = 0; k0 < K; k0 += BK) {
        // load + transpose A tile (128 rows x 16 cols)
#pragma unroll
        for (int r = 0; r < 2; r++) {
            int row = (tid >> 2) + r * 64;
            int col = (tid & 3) * 4;
            float4 v = *(const float4*)(Ablk + (size_t)row * K + k0 + col);
            As[col + 0][row] = v.x; As[col + 1][row] = v.y;
            As[col + 2][row] = v.z; As[col + 3][row] = v.w;
            float4 w = *(const float4*)(Wblk + (size_t)row * K + k0 + col);
            Ws[col + 0][row] = w.x; Ws[col + 1][row] = w.y;
            Ws[col + 2][row] = w.z; Ws[col + 3][row] = w.w;
        }
        __syncthreads();

#pragma unroll
        for (int kk = 0; kk < BK; kk++) {
            float ra[8], rb[8];
            *(float4*)&ra[0] = *(const float4*)&As[kk][tm * 8];
            *(float4*)&ra[4] = *(const float4*)&As[kk][tm * 8 + 4];
            *(float4*)&rb[0] = *(const float4*)&Ws[kk][tn * 8];
            *(float4*)&rb[4] = *(const float4*)&Ws[kk][tn * 8 + 4];
#pragma unroll
            for (int i = 0; i < 8; i++)
#pragma unroll
                for (int j = 0; j < 8; j++)
                    acc[i][j] = fmaf(ra[i], rb[j], acc[i][j]);
        }
        __syncthreads();
    }

    // epilogue with bias
#pragma unroll
    for (int i = 0; i < 8; i++) {
        int row = by * BM + tm * 8 + i;
#pragma unroll
        for (int j4 = 0; j4 < 2; j4++) {
            int col = bx * BN + tn * 8 + j4 * 4;
            float4 bv = *(const float4*)(bias + col);
            float4 o;
            o.x = acc[i][j4 * 4 + 0] + bv.x;
            o.y = acc[i][j4 * 4 + 1] + bv.y;
            o.z = acc[i][j4 * 4 + 2] + bv.z;
            o.w = acc[i][j4 * 4 + 3] + bv.w;
            *(float4*)(C + (size_t)row * N + col) = o;
        }
    }
}

// ---------------- SYRK: G[D,D] = M^T M (M is [NBL, D]) ----------------------
__global__ __launch_bounds__(256) void syrk_tn(
    const float* __restrict__ A, float* __restrict__ C)
{
    __shared__ float Ai[BK][BM + PAD];
    __shared__ float Aj[BK][BN + PAD];

    const int tid = threadIdx.x;
    const int tm = tid / 16;
    const int tn = tid % 16;
    const int i0 = blockIdx.y * BM;
    const int j0 = blockIdx.x * BN;

    float acc[8][8];
#pragma unroll
    for (int i = 0; i < 8; i++)
#pragma unroll
        for (int j = 0; j < 8; j++) acc[i][j] = 0.0f;

    for (int k0 = 0; k0 < NBL; k0 += BK) {
#pragma unroll
        for (int r = 0; r < 2; r++) {
            int idx = tid + r * 256;      // 0..511
            int row = idx >> 5;           // 0..15
            int c4  = idx & 31;           // 0..31
            *(float4*)&Ai[row][c4 * 4] =
                *(const float4*)(A + (size_t)(k0 + row) * DD + i0 + c4 * 4);
            *(float4*)&Aj[row][c4 * 4] =
                *(const float4*)(A + (size_t)(k0 + row) * DD + j0 + c4 * 4);
        }
        __syncthreads();

#pragma unroll
        for (int kk = 0; kk < BK; kk++) {
            float ra[8], rb[8];
            *(float4*)&ra[0] = *(const float4*)&Ai[kk][tm * 8];
            *(float4*)&ra[4] = *(const float4*)&Ai[kk][tm * 8 + 4];
            *(float4*)&rb[0] = *(const float4*)&Aj[kk][tn * 8];
            *(float4*)&rb[4] = *(const float4*)&Aj[kk][tn * 8 + 4];
#pragma unroll
            for (int i = 0; i < 8; i++)
#pragma unroll
                for (int j = 0; j < 8; j++)
                    acc[i][j] = fmaf(ra[i], rb[j], acc[i][j]);
        }
        __syncthreads();
    }

#pragma unroll
    for (int i = 0; i < 8; i++) {
        int row = i0 + tm * 8 + i;
#pragma unroll
        for (int j4 = 0; j4 < 2; j4++) {
            int col = j0 + tn * 8 + j4 * 4;
            float4 o;
            o.x = acc[i][j4 * 4 + 0]; o.y = acc[i][j4 * 4 + 1];
            o.z = acc[i][j4 * 4 + 2]; o.w = acc[i][j4 * 4 + 3];
            *(float4*)(C + (size_t)row * DD + col) = o;
        }
    }
}

// ---------------- Attention: flash-style, 1 thread = 1 query row ------------
// grid: (L/128, H, B), block: 128
__global__ __launch_bounds__(128) void attn_kernel(
    const float* __restrict__ Q, const float* __restrict__ K,
    const float* __restrict__ V, float* __restrict__ O)
{
    __shared__ float Ks[64][64];
    __shared__ float Vs[64][64];

    const int t = threadIdx.x;
    const int qrow = blockIdx.x * 128 + t;
    const int h = blockIdx.y;
    const int b = blockIdx.z;
    const float scale = 0.125f;   // 1/sqrt(64)

    const float* qp = Q + ((size_t)(b * LL + qrow)) * DD + h * DK;
    float q[DK], acc[DK];
#pragma unroll
    for (int d = 0; d < DK; d += 4) {
        float4 v = *(const float4*)(qp + d);
        q[d] = v.x; q[d + 1] = v.y; q[d + 2] = v.z; q[d + 3] = v.w;
        acc[d] = 0.0f; acc[d + 1] = 0.0f; acc[d + 2] = 0.0f; acc[d + 3] = 0.0f;
    }

    float m = -1e30f;
    float l = 0.0f;

    for (int k0 = 0; k0 < LL; k0 += 64) {
        __syncthreads();
        const float* kbase = K + ((size_t)(b * LL + k0)) * DD + h * DK;
        const float* vbase = V + ((size_t)(b * LL + k0)) * DD + h * DK;
#pragma unroll
        for (int i = 0; i < 8; i++) {
            int idx = t * 8 + i;          // 0..1023 (64 rows x 16 float4)
            int row = idx >> 4;
            int c4  = idx & 15;
            *(float4*)&Ks[row][c4 * 4] =
                *(const float4*)(kbase + (size_t)row * DD + c4 * 4);
            *(float4*)&Vs[row][c4 * 4] =
                *(const float4*)(vbase + (size_t)row * DD + c4 * 4);
        }
        __syncthreads();

        for (int kk = 0; kk < 64; kk++) {
            const float* kr = &Ks[kk][0];
            float s = 0.0f;
#pragma unroll
            for (int d = 0; d < DK; d++) s = fmaf(q[d], kr[d], s);
            s *= scale;
            if (s > m) {
                float f = __expf(m - s);
                m = s;
                l *= f;
#pragma unroll
                for (int d = 0; d < DK; d++) acc[d] *= f;
            }
            float p = __expf(s - m);
            l += p;
            const float* vr = &Vs[kk][0];
#pragma unroll
            for (int d = 0; d < DK; d++) acc[d] = fmaf(p, vr[d], acc[d]);
        }
    }

    float inv = 1.0f / l;
    float* op = O + ((size_t)(b * LL + qrow)) * DD + h * DK;
#pragma unroll
    for (int d = 0; d < DK; d += 4) {
        float4 o;
        o.x = acc[d] * inv; o.y = acc[d + 1] * inv;
        o.z = acc[d + 2] * inv; o.w = acc[d + 3] * inv;
        *(float4*)(op + d) = o;
    }
}

// ---------------- column means of merged -------------------------------------
__global__ void colmean_kernel(const float* __restrict__ M, float* __restrict__ mean)
{
    int col = blockIdx.x * blockDim.x + threadIdx.x;  // 1024 threads total
    float s = 0.0f;
    for (int r = 0; r < NBL; r++) s += M[(size_t)r * DD + col];
    mean[col] = s * (1.0f / (float)NBL);
}

// ---------------- DeCov: per-row partial sums (deterministic) ----------------
__global__ void decov_row(const float* __restrict__ G,
                          const float* __restrict__ mean,
                          float* __restrict__ partial)
{
    __shared__ float red[256];
    const int i = blockIdx.x;
    const float mi = mean[i];
    const float invN = 1.0f / (float)NBL;
    float s = 0.0f;
    for (int j = threadIdx.x; j < DD; j += 256) {
        if (j == i) continue;
        float c = G[(size_t)i * DD + j] * invN - mi * mean[j];
        s += c * c;
    }
    red[threadIdx.x] = s;
    __syncthreads();
    for (int off = 128; off > 0; off >>= 1) {
        if (threadIdx.x < off) red[threadIdx.x] += red[threadIdx.x + off];
        __syncthreads();
    }
    if (threadIdx.x == 0) partial[i] = red[0];
}

__global__ void decov_final(const float* __restrict__ partial, float* __restrict__ out)
{
    __shared__ float red[256];
    float s = 0.0f;
    for (int i = threadIdx.x; i < DD; i += 256) s += partial[i];
    red[threadIdx.x] = s;
    __syncthreads();
    for (int off = 128; off > 0; off >>= 1) {
        if (threadIdx.x < off) red[threadIdx.x] += red[threadIdx.x + off];
        __syncthreads();
    }
    if (threadIdx.x == 0) out[0] = 0.5f * red[0];
}

// ---------------- launch ------------------------------------------------------
extern "C" void kernel_launch(void* const* d_in, const int* in_sizes, int n_in,
                              void* d_out, int out_size)
{
    const float* x  = (const float*)d_in[0];
    const float* Wq = (const float*)d_in[1];
    const float* bq = (const float*)d_in[2];
    const float* Wk = (const float*)d_in[3];
    const float* bk = (const float*)d_in[4];
    const float* Wv = (const float*)d_in[5];
    const float* bv = (const float*)d_in[6];
    const float* Wo = (const float*)d_in[7];
    const float* bo = (const float*)d_in[8];
    float* out = (float*)d_out;

    float *Qp, *Kp, *Vp, *Mp, *Gp, *meanp, *partp;
    cudaGetSymbolAddress((void**)&Qp, g_Q);
    cudaGetSymbolAddress((void**)&Kp, g_K);
    cudaGetSymbolAddress((void**)&Vp, g_V);
    cudaGetSymbolAddress((void**)&Mp, g_M);
    cudaGetSymbolAddress((void**)&Gp, g_G);
    cudaGetSymbolAddress((void**)&meanp, g_mean);
    cudaGetSymbolAddress((void**)&partp, g_partial);

    dim3 gProj(DD / BN, MTOT / BM);   // (8, 32)
    gemm_bias_nt<<<gProj, 256>>>(x, Wq, bq, Qp, MTOT, DD, DD);
    gemm_bias_nt<<<gProj, 256>>>(x, Wk, bk, Kp, MTOT, DD, DD);
    gemm_bias_nt<<<gProj, 256>>>(x, Wv, bv, Vp, MTOT, DD, DD);

    dim3 gAttn(LL / 128, HH, BB);     // (8, 16, 4)
    attn_kernel<<<gAttn, 128>>>(Qp, Kp, Vp, Mp);

    gemm_bias_nt<<<gProj, 256>>>(Mp, Wo, bo, out, MTOT, DD, DD);

    colmean_kernel<<<DD / 256, 256>>>(Mp, meanp);

    dim3 gSyrk(DD / BN, DD / BM);     // (8, 8)
    syrk_tn<<<gSyrk, 256>>>(Mp, Gp);

    decov_row<<<DD, 256>>>(Gp, meanp, partp);
    decov_final<<<1, 256>>>(partp, out + (out_size - 1));
}

// round 3
// speedup vs baseline: 1.5376x; 1.5376x over previous
#include <cuda_runtime.h>
#include <cuda_bf16.h>
#include <math.h>
#include <stdint.h>

// Problem constants
#define BB 4
#define LL 1024
#define DD 1024
#define HH 16
#define DK 64
#define MTOT (BB * LL)          // 4096
#define NBL  (BB * LL)          // 4096

// ---------------- scratch (static device memory; no allocations) -------------
__device__ float g_Q[MTOT * DD];
__device__ float g_K[MTOT * DD];
__device__ float g_V[MTOT * DD];
__device__ float g_M[MTOT * DD];      // merged head outputs
__device__ float g_G[DD * DD];        // M^T M
__device__ float g_mean[DD];
__device__ float g_partial[DD];

__device__ __align__(16) __nv_bfloat16 g_xh[MTOT * DD];
__device__ __align__(16) __nv_bfloat16 g_xl[MTOT * DD];
__device__ __align__(16) __nv_bfloat16 g_Mh[MTOT * DD];
__device__ __align__(16) __nv_bfloat16 g_Ml[MTOT * DD];
__device__ __align__(16) __nv_bfloat16 g_Mth[DD * NBL];
__device__ __align__(16) __nv_bfloat16 g_Mtl[DD * NBL];
__device__ __align__(16) __nv_bfloat16 g_Wqh[DD * DD];
__device__ __align__(16) __nv_bfloat16 g_Wql[DD * DD];
__device__ __align__(16) __nv_bfloat16 g_Wkh[DD * DD];
__device__ __align__(16) __nv_bfloat16 g_Wkl[DD * DD];
__device__ __align__(16) __nv_bfloat16 g_Wvh[DD * DD];
__device__ __align__(16) __nv_bfloat16 g_Wvl[DD * DD];
__device__ __align__(16) __nv_bfloat16 g_Woh[DD * DD];
__device__ __align__(16) __nv_bfloat16 g_Wol[DD * DD];

// ---------------- small PTX helpers ------------------------------------------
__device__ __forceinline__ uint32_t smem_u32(const void* p) {
    uint32_t a;
    asm("{ .reg .u64 t; cvta.to.shared.u64 t, %1; cvt.u32.u64 %0, t; }"
        : "=r"(a) : "l"(p));
    return a;
}

__device__ __forceinline__ void cp_async16(uint32_t saddr, const void* gptr) {
    asm volatile("cp.async.ca.shared.global [%0], [%1], 16;"
                 :: "r"(saddr), "l"(gptr));
}
__device__ __forceinline__ void cp_commit() {
    asm volatile("cp.async.commit_group;" ::: "memory");
}
template <int N>
__device__ __forceinline__ void cp_wait() {
    asm volatile("cp.async.wait_group %0;" :: "n"(N) : "memory");
}

__device__ __forceinline__ void ldm_x4(uint32_t (&r)[4], uint32_t addr) {
    asm volatile("ldmatrix.sync.aligned.m8n8.x4.shared.b16 {%0,%1,%2,%3}, [%4];"
                 : "=r"(r[0]), "=r"(r[1]), "=r"(r[2]), "=r"(r[3]) : "r"(addr));
}

__device__ __forceinline__ void mma16816(float (&c)[4], const uint32_t (&a)[4],
                                         uint32_t b0, uint32_t b1) {
    asm volatile(
        "mma.sync.aligned.m16n8k16.row.col.f32.bf16.bf16.f32 "
        "{%0,%1,%2,%3}, {%4,%5,%6,%7}, {%8,%9}, {%0,%1,%2,%3};"
        : "+f"(c[0]), "+f"(c[1]), "+f"(c[2]), "+f"(c[3])
        : "r"(a[0]), "r"(a[1]), "r"(a[2]), "r"(a[3]), "r"(b0), "r"(b1));
}

// packed f32x2 ops (Blackwell)
__device__ __forceinline__ uint64_t fma2(uint64_t a, uint64_t b, uint64_t c) {
    uint64_t d;
    asm("fma.rn.f32x2 %0, %1, %2, %3;" : "=l"(d) : "l"(a), "l"(b), "l"(c));
    return d;
}
__device__ __forceinline__ uint64_t mul2(uint64_t a, uint64_t b) {
    uint64_t d;
    asm("mul.rn.f32x2 %0, %1, %2;" : "=l"(d) : "l"(a), "l"(b));
    return d;
}
__device__ __forceinline__ uint64_t add2(uint64_t a, uint64_t b) {
    uint64_t d;
    asm("add.rn.f32x2 %0, %1, %2;" : "=l"(d) : "l"(a), "l"(b));
    return d;
}
__device__ __forceinline__ uint64_t pack2(float lo, float hi) {
    uint64_t d;
    asm("mov.b64 %0, {%1, %2};" : "=l"(d) : "f"(lo), "f"(hi));
    return d;
}
__device__ __forceinline__ void unpack2(float& lo, float& hi, uint64_t v) {
    asm("mov.b64 {%0, %1}, %2;" : "=f"(lo), "=f"(hi) : "l"(v));
}

// ---------------- fp32 -> (bf16 hi, bf16 lo) split ---------------------------
struct __align__(8) bf16x4 { __nv_bfloat16 a, b, c, d; };

__global__ __launch_bounds__(256) void split_kernel(
    const float* __restrict__ X, __nv_bfloat16* __restrict__ Xh,
    __nv_bfloat16* __restrict__ Xl, int n4)
{
    int i = blockIdx.x * 256 + threadIdx.x;
    if (i >= n4) return;
    float4 v = ((const float4*)X)[i];
    __nv_bfloat16 h0 = __float2bfloat16(v.x);
    __nv_bfloat16 h1 = __float2bfloat16(v.y);
    __nv_bfloat16 h2 = __float2bfloat16(v.z);
    __nv_bfloat16 h3 = __float2bfloat16(v.w);
    __nv_bfloat16 l0 = __float2bfloat16(v.x - __bfloat162float(h0));
    __nv_bfloat16 l1 = __float2bfloat16(v.y - __bfloat162float(h1));
    __nv_bfloat16 l2 = __float2bfloat16(v.z - __bfloat162float(h2));
    __nv_bfloat16 l3 = __float2bfloat16(v.w - __bfloat162float(h3));
    bf16x4 hv = {h0, h1, h2, h3};
    bf16x4 lv = {l0, l1, l2, l3};
    ((bf16x4*)Xh)[i] = hv;
    ((bf16x4*)Xl)[i] = lv;
}

// ---------------- transpose + split: M[NBL][DD] -> T[DD][NBL] ----------------
__global__ __launch_bounds__(256) void transpose_split_kernel(
    const float* __restrict__ Msrc,
    __nv_bfloat16* __restrict__ Th, __nv_bfloat16* __restrict__ Tl)
{
    __shared__ float tile[32][33];
    int bx = blockIdx.x;
    int by = blockIdx.y;
    int tx = threadIdx.x;
    int ty = threadIdx.y;
#pragma unroll
    for (int j = 0; j < 32; j += 8)
        tile[ty + j][tx] = Msrc[(size_t)(by * 32 + ty + j) * DD + bx * 32 + tx];
    __syncthreads();
#pragma unroll
    for (int j = 0; j < 32; j += 8) {
        float v = tile[tx][ty + j];
        __nv_bfloat16 h = __float2bfloat16(v);
        __nv_bfloat16 l = __float2bfloat16(v - __bfloat162float(h));
        size_t off = (size_t)(bx * 32 + ty + j) * NBL + by * 32 + tx;
        Th[off] = h;
        Tl[off] = l;
    }
}

// ---------------- mma.sync GEMM: C[128bm,128bn] = A@B^T (+bias) --------------
// A = Ah + Al, B = Bh + Bl (bf16 hi/lo splits, K-major rows).
// 3 passes: (Ah,Bh), (Ah,Bl), (Al,Bh); fp32 register accumulation.
// smem: double-buffered 128x64 bf16 tiles for A and B, pitch 144B.
#define GPITCH 144              // bytes per smem row (64 bf16 + 8 pad)
#define GTILE  (128 * GPITCH)   // 18432 B
#define GBUF   (2 * GTILE)      // A+B for one stage
#define GSMEM  (2 * GBUF)       // double buffer: 73728 B

__global__ __launch_bounds__(256) void gemm_mma(
    const __nv_bfloat16* __restrict__ Ah, const __nv_bfloat16* __restrict__ Al,
    const __nv_bfloat16* __restrict__ Bh, const __nv_bfloat16* __restrict__ Bl,
    const float* __restrict__ bias, float* __restrict__ C,
    int K, int N)
{
    extern __shared__ __align__(16) char smem[];
    const uint32_t sbase = smem_u32(smem);
    const int tid = threadIdx.x;
    const int lane = tid & 31;
    const int wid = tid >> 5;
    const int wm = wid >> 2;         // 0..1  (64 rows each)
    const int wn = wid & 3;          // 0..3  (32 cols each)
    const int bx = blockIdx.x;
    const int by = blockIdx.y;

    const __nv_bfloat16* pA[3] = {Ah, Ah, Al};
    const __nv_bfloat16* pB[3] = {Bh, Bl, Bh};

    const int Kc = K >> 6;           // 64-element chunks per pass
    const int total = 3 * Kc;

    float c[4][4][4];
#pragma unroll
    for (int i = 0; i < 4; i++)
#pragma unroll
        for (int j = 0; j < 4; j++)
#pragma unroll
            for (int f = 0; f < 4; f++) c[i][j][f] = 0.0f;

    // chunk loader: 256 threads x 4 iters x (A16B + B16B)
    auto load_chunk = [&](int g, int buf) {
        int p = g / Kc;
        int kk = g - p * Kc;
        const __nv_bfloat16* Abase = pA[p] + (size_t)by * 128 * K + kk * 64;
        const __nv_bfloat16* Bbase = pB[p] + (size_t)bx * 128 * K + kk * 64;
        uint32_t aS = sbase + buf * GBUF;
        uint32_t bS = aS + GTILE;
#pragma unroll
        for (int j = 0; j < 4; j++) {
            int lin = tid + j * 256;        // 0..1023
            int row = lin >> 3;             // 0..127
            int seg = lin & 7;              // 16B segment
            cp_async16(aS + row * GPITCH + seg * 16,
                       Abase + (size_t)row * K + seg * 8);
            cp_async16(bS + row * GPITCH + seg * 16,
                       Bbase + (size_t)row * K + seg * 8);
        }
        cp_commit();
    };

    load_chunk(0, 0);

    for (int g = 0; g < total; g++) {
        if (g + 1 < total) {
            load_chunk(g + 1, (g + 1) & 1);
            cp_wait<1>();
        } else {
            cp_wait<0>();
        }
        __syncthreads();

        const uint32_t aS = sbase + (g & 1) * GBUF;
        const uint32_t bS = aS + GTILE;
#pragma unroll
        for (int s = 0; s < 4; s++) {       // four k16 steps
            uint32_t a[4][4];
#pragma unroll
            for (int i = 0; i < 4; i++) {
                int row = wm * 64 + i * 16 + (lane & 15);
                ldm_x4(a[i], aS + row * GPITCH + s * 32 + ((lane >> 4) * 16));
            }
            uint32_t b[2][4];
#pragma unroll
            for (int j = 0; j < 2; j++) {
                int row = wn * 32 + j * 16 + ((lane >> 4) << 3) + (lane & 7);
                int off = ((lane >> 3) & 1) * 16;
                ldm_x4(b[j], bS + row * GPITCH + s * 32 + off);
            }
#pragma unroll
            for (int i = 0; i < 4; i++) {
#pragma unroll
                for (int j = 0; j < 2; j++) {
                    mma16816(c[i][2 * j], a[i], b[j][0], b[j][1]);
                    mma16816(c[i][2 * j + 1], a[i], b[j][2], b[j][3]);
                }
            }
        }
        __syncthreads();
    }

    // epilogue
#pragma unroll
    for (int i = 0; i < 4; i++) {
        int r0 = by * 128 + wm * 64 + i * 16 + (lane >> 2);
#pragma unroll
        for (int nt = 0; nt < 4; nt++) {
            int col = bx * 128 + wn * 32 + nt * 8 + (lane & 3) * 2;
            float bx0 = 0.0f, bx1 = 0.0f;
            if (bias) { bx0 = bias[col]; bx1 = bias[col + 1]; }
            float2 v0, v1;
            v0.x = c[i][nt][0] + bx0; v0.y = c[i][nt][1] + bx1;
            v1.x = c[i][nt][2] + bx0; v1.y = c[i][nt][3] + bx1;
            *(float2*)(C + (size_t)r0 * N + col) = v0;
            *(float2*)(C + (size_t)(r0 + 8) * N + col) = v1;
        }
    }
}

// ---------------- Attention: flash-style, f32x2 packed math ------------------
__global__ __launch_bounds__(128) void attn_kernel(
    const float* __restrict__ Q, const float* __restrict__ K,
    const float* __restrict__ V, float* __restrict__ O)
{
    __shared__ __align__(16) float Ks[64][64];
    __shared__ __align__(16) float Vs[64][64];

    const int t = threadIdx.x;
    const int qrow = blockIdx.x * 128 + t;
    const int h = blockIdx.y;
    const int b = blockIdx.z;
    const float scale = 0.125f;

    const float* qp = Q + ((size_t)(b * LL + qrow)) * DD + h * DK;
    uint64_t q2[32], acc2[32];
#pragma unroll
    for (int d = 0; d < 16; d++) {
        ulonglong2 v = *(const ulonglong2*)(qp + d * 4);
        q2[2 * d] = v.x; q2[2 * d + 1] = v.y;
        acc2[2 * d] = 0ull; acc2[2 * d + 1] = 0ull;
    }

    float m = -1e30f;
    float l = 0.0f;

    for (int k0 = 0; k0 < LL; k0 += 64) {
        __syncthreads();
        const float* kbase = K + ((size_t)(b * LL + k0)) * DD + h * DK;
        const float* vbase = V + ((size_t)(b * LL + k0)) * DD + h * DK;
#pragma unroll
        for (int i = 0; i < 8; i++) {
            int idx = t * 8 + i;
            int row = idx >> 4;
            int c4  = idx & 15;
            *(float4*)&Ks[row][c4 * 4] =
                *(const float4*)(kbase + (size_t)row * DD + c4 * 4);
            *(float4*)&Vs[row][c4 * 4] =
                *(const float4*)(vbase + (size_t)row * DD + c4 * 4);
        }
        __syncthreads();

        for (int kk = 0; kk < 64; kk++) {
            const ulonglong2* kr = (const ulonglong2*)&Ks[kk][0];
            uint64_t sA = 0ull, sB = 0ull;
#pragma unroll
            for (int r = 0; r < 16; r++) {
                ulonglong2 kv = kr[r];
                sA = fma2(q2[2 * r], kv.x, sA);
                sB = fma2(q2[2 * r + 1], kv.y, sB);
            }
            float lo, hi;
            unpack2(lo, hi, add2(sA, sB));
            float s = (lo + hi) * scale;

            if (s > m) {
                float f = __expf(m - s);
                m = s;
                l *= f;
                uint64_t f2 = pack2(f, f);
#pragma unroll
                for (int d = 0; d < 32; d++) acc2[d] = mul2(acc2[d], f2);
            }
            float p = __expf(s - m);
            l += p;
            uint64_t p2 = pack2(p, p);
            const ulonglong2* vr = (const ulonglong2*)&Vs[kk][0];
#pragma unroll
            for (int r = 0; r < 16; r++) {
                ulonglong2 vv = vr[r];
                acc2[2 * r] = fma2(p2, vv.x, acc2[2 * r]);
                acc2[2 * r + 1] = fma2(p2, vv.y, acc2[2 * r + 1]);
            }
        }
    }

    float inv = 1.0f / l;
    uint64_t inv2 = pack2(inv, inv);
    float* op = O + ((size_t)(b * LL + qrow)) * DD + h * DK;
#pragma unroll
    for (int d = 0; d < 16; d++) {
        ulonglong2 o;
        o.x = mul2(acc2[2 * d], inv2);
        o.y = mul2(acc2[2 * d + 1], inv2);
        *(ulonglong2*)(op + d * 4) = o;
    }
}

// ---------------- column means of merged -------------------------------------
__global__ void colmean_kernel(const float* __restrict__ M, float* __restrict__ mean)
{
    int col = blockIdx.x * blockDim.x + threadIdx.x;
    float s = 0.0f;
    for (int r = 0; r < NBL; r++) s += M[(size_t)r * DD + col];
    mean[col] = s * (1.0f / (float)NBL);
}

// ---------------- DeCov partial sums (deterministic) -------------------------
__global__ void decov_row(const float* __restrict__ G,
                          const float* __restrict__ mean,
                          float* __restrict__ partial)
{
    __shared__ float red[256];
    const int i = blockIdx.x;
    const float mi = mean[i];
    const float invN = 1.0f / (float)NBL;
    float s = 0.0f;
    for (int j = threadIdx.x; j < DD; j += 256) {
        if (j == i) continue;
        float c = G[(size_t)i * DD + j] * invN - mi * mean[j];
        s += c * c;
    }
    red[threadIdx.x] = s;
    __syncthreads();
    for (int off = 128; off > 0; off >>= 1) {
        if (threadIdx.x < off) red[threadIdx.x] += red[threadIdx.x + off];
        __syncthreads();
    }
    if (threadIdx.x == 0) partial[i] = red[0];
}

__global__ void decov_final(const float* __restrict__ partial, float* __restrict__ out)
{
    __shared__ float red[256];
    float s = 0.0f;
    for (int i = threadIdx.x; i < DD; i += 256) s += partial[i];
    red[threadIdx.x] = s;
    __syncthreads();
    for (int off = 128; off > 0; off >>= 1) {
        if (threadIdx.x < off) red[threadIdx.x] += red[threadIdx.x + off];
        __syncthreads();
    }
    if (threadIdx.x == 0) out[0] = 0.5f * red[0];
}

// ---------------- launch ------------------------------------------------------
extern "C" void kernel_launch(void* const* d_in, const int* in_sizes, int n_in,
                              void* d_out, int out_size)
{
    const float* x  = (const float*)d_in[0];
    const float* Wq = (const float*)d_in[1];
    const float* bq = (const float*)d_in[2];
    const float* Wk = (const float*)d_in[3];
    const float* bk = (const float*)d_in[4];
    const float* Wv = (const float*)d_in[5];
    const float* bv = (const float*)d_in[6];
    const float* Wo = (const float*)d_in[7];
    const float* bo = (const float*)d_in[8];
    float* out = (float*)d_out;

    float *Qp, *Kp, *Vp, *Mp, *Gp, *meanp, *partp;
    cudaGetSymbolAddress((void**)&Qp, g_Q);
    cudaGetSymbolAddress((void**)&Kp, g_K);
    cudaGetSymbolAddress((void**)&Vp, g_V);
    cudaGetSymbolAddress((void**)&Mp, g_M);
    cudaGetSymbolAddress((void**)&Gp, g_G);
    cudaGetSymbolAddress((void**)&meanp, g_mean);
    cudaGetSymbolAddress((void**)&partp, g_partial);

    __nv_bfloat16 *xh, *xl, *Mh, *Ml, *Mth, *Mtl;
    __nv_bfloat16 *Wqh, *Wql, *Wkh, *Wkl, *Wvh, *Wvl, *Woh, *Wol;
    cudaGetSymbolAddress((void**)&xh, g_xh);
    cudaGetSymbolAddress((void**)&xl, g_xl);
    cudaGetSymbolAddress((void**)&Mh, g_Mh);
    cudaGetSymbolAddress((void**)&Ml, g_Ml);
    cudaGetSymbolAddress((void**)&Mth, g_Mth);
    cudaGetSymbolAddress((void**)&Mtl, g_Mtl);
    cudaGetSymbolAddress((void**)&Wqh, g_Wqh);
    cudaGetSymbolAddress((void**)&Wql, g_Wql);
    cudaGetSymbolAddress((void**)&Wkh, g_Wkh);
    cudaGetSymbolAddress((void**)&Wkl, g_Wkl);
    cudaGetSymbolAddress((void**)&Wvh, g_Wvh);
    cudaGetSymbolAddress((void**)&Wvl, g_Wvl);
    cudaGetSymbolAddress((void**)&Woh, g_Woh);
    cudaGetSymbolAddress((void**)&Wol, g_Wol);

    cudaFuncSetAttribute(gemm_mma, cudaFuncAttributeMaxDynamicSharedMemorySize,
                         GSMEM);

    // splits
    const int n4x = MTOT * DD / 4;
    const int n4w = DD * DD / 4;
    split_kernel<<<n4x / 256, 256>>>(x, xh, xl, n4x);
    split_kernel<<<n4w / 256, 256>>>(Wq, Wqh, Wql, n4w);
    split_kernel<<<n4w / 256, 256>>>(Wk, Wkh, Wkl, n4w);
    split_kernel<<<n4w / 256, 256>>>(Wv, Wvh, Wvl, n4w);
    split_kernel<<<n4w / 256, 256>>>(Wo, Woh, Wol, n4w);

    // projection GEMMs (tensor cores via mma.sync)
    dim3 gProj(DD / 128, MTOT / 128);   // (8, 32)
    gemm_mma<<<gProj, 256, GSMEM>>>(xh, xl, Wqh, Wql, bq, Qp, DD, DD);
    gemm_mma<<<gProj, 256, GSMEM>>>(xh, xl, Wkh, Wkl, bk, Kp, DD, DD);
    gemm_mma<<<gProj, 256, GSMEM>>>(xh, xl, Wvh, Wvl, bv, Vp, DD, DD);

    // attention
    dim3 gAttn(LL / 128, HH, BB);
    attn_kernel<<<gAttn, 128>>>(Qp, Kp, Vp, Mp);

    // split merged output (row-major + transposed)
    split_kernel<<<n4x / 256, 256>>>(Mp, Mh, Ml, n4x);
    transpose_split_kernel<<<dim3(DD / 32, NBL / 32), dim3(32, 8)>>>(Mp, Mth, Mtl);

    // output projection
    gemm_mma<<<gProj, 256, GSMEM>>>(Mh, Ml, Woh, Wol, bo, out, DD, DD);

    // DeCov path
    colmean_kernel<<<DD / 256, 256>>>(Mp, meanp);
    dim3 gSyrk(DD / 128, DD / 128);     // (8, 8)
    gemm_mma<<<gSyrk, 256, GSMEM>>>(Mth, Mtl, Mth, Mtl, nullptr, Gp, NBL, DD);
    decov_row<<<DD, 256>>>(Gp, meanp, partp);
    decov_final<<<1, 256>>>(partp, out + (out_size - 1));
}

// round 4
// speedup vs baseline: 1.7279x; 1.1238x over previous
#include <cuda_runtime.h>
#include <cuda_fp16.h>
#include <cuda_bf16.h>
#include <math.h>
#include <stdint.h>

// Problem constants
#define BB 4
#define LL 1024
#define DD 1024
#define HH 16
#define DK 64
#define MTOT (BB * LL)          // 4096
#define NBL  (BB * LL)          // 4096

// ---------------- scratch (static device memory; no allocations) -------------
__device__ float g_QKV[MTOT * 3 * DD];    // fused Q|K|V, row stride 3072
__device__ float g_M[MTOT * DD];          // merged head outputs
__device__ float g_G[DD * DD];            // M^T M
__device__ float g_mean[DD];
__device__ float g_partial[DD];
__device__ float g_Opart[2 * MTOT * DD];  // out-proj split-K partials
__device__ float g_Gpart[4 * DD * DD];    // syrk split-K partials
__device__ float g_bqkv[3 * DD];

__device__ __align__(16) __half g_xh[MTOT * DD];
__device__ __align__(16) __half g_xl[MTOT * DD];
__device__ __align__(16) __half g_Mh[MTOT * DD];
__device__ __align__(16) __half g_Ml[MTOT * DD];
__device__ __align__(16) __half g_Mth[DD * NBL];
__device__ __align__(16) __half g_Mtl[DD * NBL];
__device__ __align__(16) __half g_Wqkvh[3 * DD * DD];
__device__ __align__(16) __half g_Woh[DD * DD];

// ---------------- small PTX helpers ------------------------------------------
__device__ __forceinline__ uint32_t smem_u32(const void* p) {
    uint32_t a;
    asm("{ .reg .u64 t; cvta.to.shared.u64 t, %1; cvt.u32.u64 %0, t; }"
        : "=r"(a) : "l"(p));
    return a;
}

__device__ __forceinline__ void cp_async16(uint32_t saddr, const void* gptr) {
    asm volatile("cp.async.ca.shared.global [%0], [%1], 16;"
                 :: "r"(saddr), "l"(gptr));
}
__device__ __forceinline__ void cp_commit() {
    asm volatile("cp.async.commit_group;" ::: "memory");
}
template <int N>
__device__ __forceinline__ void cp_wait() {
    asm volatile("cp.async.wait_group %0;" :: "n"(N) : "memory");
}

__device__ __forceinline__ void ldm_x4(uint32_t (&r)[4], uint32_t addr) {
    asm volatile("ldmatrix.sync.aligned.m8n8.x4.shared.b16 {%0,%1,%2,%3}, [%4];"
                 : "=r"(r[0]), "=r"(r[1]), "=r"(r[2]), "=r"(r[3]) : "r"(addr));
}

__device__ __forceinline__ void mma16816(float (&c)[4], const uint32_t (&a)[4],
                                         uint32_t b0, uint32_t b1) {
    asm volatile(
        "mma.sync.aligned.m16n8k16.row.col.f32.f16.f16.f32 "
        "{%0,%1,%2,%3}, {%4,%5,%6,%7}, {%8,%9}, {%0,%1,%2,%3};"
        : "+f"(c[0]), "+f"(c[1]), "+f"(c[2]), "+f"(c[3])
        : "r"(a[0]), "r"(a[1]), "r"(a[2]), "r"(a[3]), "r"(b0), "r"(b1));
}

// packed f32x2 ops (Blackwell)
__device__ __forceinline__ uint64_t fma2(uint64_t a, uint64_t b, uint64_t c) {
    uint64_t d;
    asm("fma.rn.f32x2 %0, %1, %2, %3;" : "=l"(d) : "l"(a), "l"(b), "l"(c));
    return d;
}
__device__ __forceinline__ uint64_t mul2(uint64_t a, uint64_t b) {
    uint64_t d;
    asm("mul.rn.f32x2 %0, %1, %2;" : "=l"(d) : "l"(a), "l"(b));
    return d;
}
__device__ __forceinline__ uint64_t add2(uint64_t a, uint64_t b) {
    uint64_t d;
    asm("add.rn.f32x2 %0, %1, %2;" : "=l"(d) : "l"(a), "l"(b));
    return d;
}
__device__ __forceinline__ uint64_t pack2(float lo, float hi) {
    uint64_t d;
    asm("mov.b64 %0, {%1, %2};" : "=l"(d) : "f"(lo), "f"(hi));
    return d;
}
__device__ __forceinline__ void unpack2(float& lo, float& hi, uint64_t v) {
    asm("mov.b64 {%0, %1}, %2;" : "=f"(lo), "=f"(hi) : "l"(v));
}

// ---------------- fp32 -> (fp16 hi, fp16 lo) split ---------------------------
struct __align__(8) half4 { __half a, b, c, d; };

__global__ __launch_bounds__(256) void split_fp16(
    const float* __restrict__ X, __half* __restrict__ Xh,
    __half* __restrict__ Xl, int n4)
{
    int i = blockIdx.x * 256 + threadIdx.x;
    if (i >= n4) return;
    float4 v = ((const float4*)X)[i];
    __half h0 = __float2half_rn(v.x);
    __half h1 = __float2half_rn(v.y);
    __half h2 = __float2half_rn(v.z);
    __half h3 = __float2half_rn(v.w);
    __half l0 = __float2half_rn(v.x - __half2float(h0));
    __half l1 = __float2half_rn(v.y - __half2float(h1));
    __half l2 = __float2half_rn(v.z - __half2float(h2));
    __half l3 = __float2half_rn(v.w - __half2float(h3));
    half4 hv = {h0, h1, h2, h3};
    half4 lv = {l0, l1, l2, l3};
    ((half4*)Xh)[i] = hv;
    ((half4*)Xl)[i] = lv;
}

__global__ __launch_bounds__(256) void round_fp16(
    const float* __restrict__ X, __half* __restrict__ Xh, int n4)
{
    int i = blockIdx.x * 256 + threadIdx.x;
    if (i >= n4) return;
    float4 v = ((const float4*)X)[i];
    half4 hv = {__float2half_rn(v.x), __float2half_rn(v.y),
                __float2half_rn(v.z), __float2half_rn(v.w)};
    ((half4*)Xh)[i] = hv;
}

// ---------------- transpose + split: M[NBL][DD] -> T[DD][NBL] ----------------
__global__ __launch_bounds__(256) void transpose_split_fp16(
    const float* __restrict__ Msrc,
    __half* __restrict__ Th, __half* __restrict__ Tl)
{
    __shared__ float tile[32][33];
    int bx = blockIdx.x;
    int by = blockIdx.y;
    int tx = threadIdx.x;
    int ty = threadIdx.y;
#pragma unroll
    for (int j = 0; j < 32; j += 8)
        tile[ty + j][tx] = Msrc[(size_t)(by * 32 + ty + j) * DD + bx * 32 + tx];
    __syncthreads();
#pragma unroll
    for (int j = 0; j < 32; j += 8) {
        float v = tile[tx][ty + j];
        __half h = __float2half_rn(v);
        __half l = __float2half_rn(v - __half2float(h));
        size_t off = (size_t)(bx * 32 + ty + j) * NBL + by * 32 + tx;
        Th[off] = h;
        Tl[off] = l;
    }
}

// ---------------- mma.sync GEMM (2-pass fp16 split, optional split-K) --------
// C[128bm,128bn] = (Ah+Al) @ Bh^T (+bias).  All rows K-major, stride lda.
// gridDim.z = nsplit; split s handles K-range [s*Ksl, (s+1)*Ksl).
// nsplit==1: write C (+bias).  nsplit>1: write Cpart[s*M*N + ...].
#define GPITCH 144              // bytes per smem row (64 fp16 + pad)
#define GTILE  (128 * GPITCH)   // 18432 B
#define GBUF   (2 * GTILE)
#define GSMEM  (2 * GBUF)       // 73728 B

__global__ __launch_bounds__(256) void gemm2(
    const __half* __restrict__ Ah, const __half* __restrict__ Al,
    const __half* __restrict__ Bh, const float* __restrict__ bias,
    float* __restrict__ C, float* __restrict__ Cpart,
    int lda, int Ksl, int N)
{
    extern __shared__ __align__(16) char smem[];
    const uint32_t sbase = smem_u32(smem);
    const int tid = threadIdx.x;
    const int lane = tid & 31;
    const int wid = tid >> 5;
    const int wm = wid >> 2;
    const int wn = wid & 3;
    const int bx = blockIdx.x;
    const int by = blockIdx.y;
    const int split = blockIdx.z;
    const int nsplit = gridDim.z;
    const int M = gridDim.y * 128;

    const __half* pA[2] = {Ah, Al};
    const int Kc = Ksl >> 6;
    const int total = 2 * Kc;

    float c[4][4][4];
#pragma unroll
    for (int i = 0; i < 4; i++)
#pragma unroll
        for (int j = 0; j < 4; j++)
#pragma unroll
            for (int f = 0; f < 4; f++) c[i][j][f] = 0.0f;

    auto load_chunk = [&](int g, int buf) {
        int p = (g >= Kc) ? 1 : 0;
        int kk = g - p * Kc;
        const __half* Abase = pA[p] + (size_t)by * 128 * lda + split * Ksl + kk * 64;
        const __half* Bbase = Bh + (size_t)bx * 128 * lda + split * Ksl + kk * 64;
        uint32_t aS = sbase + buf * GBUF;
        uint32_t bS = aS + GTILE;
#pragma unroll
        for (int j = 0; j < 4; j++) {
            int lin = tid + j * 256;
            int row = lin >> 3;
            int seg = lin & 7;
            cp_async16(aS + row * GPITCH + seg * 16,
                       Abase + (size_t)row * lda + seg * 8);
            cp_async16(bS + row * GPITCH + seg * 16,
                       Bbase + (size_t)row * lda + seg * 8);
        }
        cp_commit();
    };

    load_chunk(0, 0);

    for (int g = 0; g < total; g++) {
        if (g + 1 < total) {
            load_chunk(g + 1, (g + 1) & 1);
            cp_wait<1>();
        } else {
            cp_wait<0>();
        }
        __syncthreads();

        const uint32_t aS = sbase + (g & 1) * GBUF;
        const uint32_t bS = aS + GTILE;
#pragma unroll
        for (int s = 0; s < 4; s++) {
            uint32_t a[4][4];
#pragma unroll
            for (int i = 0; i < 4; i++) {
                int row = wm * 64 + i * 16 + (lane & 15);
                ldm_x4(a[i], aS + row * GPITCH + s * 32 + ((lane >> 4) * 16));
            }
            uint32_t b[2][4];
#pragma unroll
            for (int j = 0; j < 2; j++) {
                int row = wn * 32 + j * 16 + ((lane >> 4) << 3) + (lane & 7);
                int off = ((lane >> 3) & 1) * 16;
                ldm_x4(b[j], bS + row * GPITCH + s * 32 + off);
            }
#pragma unroll
            for (int i = 0; i < 4; i++) {
#pragma unroll
                for (int j = 0; j < 2; j++) {
                    mma16816(c[i][2 * j], a[i], b[j][0], b[j][1]);
                    mma16816(c[i][2 * j + 1], a[i], b[j][2], b[j][3]);
                }
            }
        }
        __syncthreads();
    }

    float* dst = (nsplit == 1) ? C : (Cpart + (size_t)split * M * N);
    const bool addb = (nsplit == 1) && (bias != nullptr);
#pragma unroll
    for (int i = 0; i < 4; i++) {
        int r0 = by * 128 + wm * 64 + i * 16 + (lane >> 2);
#pragma unroll
        for (int nt = 0; nt < 4; nt++) {
            int col = bx * 128 + wn * 32 + nt * 8 + (lane & 3) * 2;
            float bx0 = 0.0f, bx1 = 0.0f;
            if (addb) { bx0 = bias[col]; bx1 = bias[col + 1]; }
            float2 v0, v1;
            v0.x = c[i][nt][0] + bx0; v0.y = c[i][nt][1] + bx1;
            v1.x = c[i][nt][2] + bx0; v1.y = c[i][nt][3] + bx1;
            *(float2*)(dst + (size_t)r0 * N + col) = v0;
            *(float2*)(dst + (size_t)(r0 + 8) * N + col) = v1;
        }
    }
}

// ---------------- split-K reduce ---------------------------------------------
__global__ __launch_bounds__(256) void reduce_parts(
    const float* __restrict__ parts, int nparts,
    const float* __restrict__ bias, float* __restrict__ out,
    int MN, int N)
{
    int i = blockIdx.x * 256 + threadIdx.x;   // float4 index
    if (i >= MN / 4) return;
    float4 s = ((const float4*)parts)[i];
    for (int p = 1; p < nparts; p++) {
        float4 v = ((const float4*)(parts + (size_t)p * MN))[i];
        s.x += v.x; s.y += v.y; s.z += v.z; s.w += v.w;
    }
    if (bias) {
        int col = (i * 4) % N;
        float4 bv = *(const float4*)(bias + col);
        s.x += bv.x; s.y += bv.y; s.z += bv.z; s.w += bv.w;
    }
    ((float4*)out)[i] = s;
}

// ---------------- Attention: flash-style, f32x2 packed math ------------------
// Reads fused QKV buffer (row stride 3*DD): Q at +0, K at +DD, V at +2*DD.
__global__ __launch_bounds__(128) void attn_kernel(
    const float* __restrict__ QKV, float* __restrict__ O)
{
    __shared__ __align__(16) float Ks[64][64];
    __shared__ __align__(16) float Vs[64][64];

    const int t = threadIdx.x;
    const int qrow = blockIdx.x * 128 + t;
    const int h = blockIdx.y;
    const int b = blockIdx.z;
    const float scale = 0.125f;
    const int RS = 3 * DD;

    const float* qp = QKV + ((size_t)(b * LL + qrow)) * RS + h * DK;
    uint64_t q2[32], acc2[32];
#pragma unroll
    for (int d = 0; d < 16; d++) {
        ulonglong2 v = *(const ulonglong2*)(qp + d * 4);
        q2[2 * d] = v.x; q2[2 * d + 1] = v.y;
        acc2[2 * d] = 0ull; acc2[2 * d + 1] = 0ull;
    }

    float m = -1e30f;
    float l = 0.0f;

    for (int k0 = 0; k0 < LL; k0 += 64) {
        __syncthreads();
        const float* kbase = QKV + ((size_t)(b * LL + k0)) * RS + DD + h * DK;
        const float* vbase = QKV + ((size_t)(b * LL + k0)) * RS + 2 * DD + h * DK;
#pragma unroll
        for (int i = 0; i < 8; i++) {
            int idx = t * 8 + i;
            int row = idx >> 4;
            int c4  = idx & 15;
            *(float4*)&Ks[row][c4 * 4] =
                *(const float4*)(kbase + (size_t)row * RS + c4 * 4);
            *(float4*)&Vs[row][c4 * 4] =
                *(const float4*)(vbase + (size_t)row * RS + c4 * 4);
        }
        __syncthreads();

        for (int kk = 0; kk < 64; kk++) {
            const ulonglong2* kr = (const ulonglong2*)&Ks[kk][0];
            uint64_t sA = 0ull, sB = 0ull;
#pragma unroll
            for (int r = 0; r < 16; r++) {
                ulonglong2 kv = kr[r];
                sA = fma2(q2[2 * r], kv.x, sA);
                sB = fma2(q2[2 * r + 1], kv.y, sB);
            }
            float lo, hi;
            unpack2(lo, hi, add2(sA, sB));
            float s = (lo + hi) * scale;

            if (s > m) {
                float f = __expf(m - s);
                m = s;
                l *= f;
                uint64_t f2 = pack2(f, f);
#pragma unroll
                for (int d = 0; d < 32; d++) acc2[d] = mul2(acc2[d], f2);
            }
            float p = __expf(s - m);
            l += p;
            uint64_t p2 = pack2(p, p);
            const ulonglong2* vr = (const ulonglong2*)&Vs[kk][0];
#pragma unroll
            for (int r = 0; r < 16; r++) {
                ulonglong2 vv = vr[r];
                acc2[2 * r] = fma2(p2, vv.x, acc2[2 * r]);
                acc2[2 * r + 1] = fma2(p2, vv.y, acc2[2 * r + 1]);
            }
        }
    }

    float inv = 1.0f / l;
    uint64_t inv2 = pack2(inv, inv);
    float* op = O + ((size_t)(b * LL + qrow)) * DD + h * DK;
#pragma unroll
    for (int d = 0; d < 16; d++) {
        ulonglong2 o;
        o.x = mul2(acc2[2 * d], inv2);
        o.y = mul2(acc2[2 * d + 1], inv2);
        *(ulonglong2*)(op + d * 4) = o;
    }
}

// ---------------- column means of merged -------------------------------------
__global__ void colmean_kernel(const float* __restrict__ M, float* __restrict__ mean)
{
    int col = blockIdx.x * blockDim.x + threadIdx.x;
    float s = 0.0f;
    for (int r = 0; r < NBL; r++) s += M[(size_t)r * DD + col];
    mean[col] = s * (1.0f / (float)NBL);
}

// ---------------- DeCov partial sums (deterministic) -------------------------
__global__ void decov_row(const float* __restrict__ G,
                          const float* __restrict__ mean,
                          float* __restrict__ partial)
{
    __shared__ float red[256];
    const int i = blockIdx.x;
    const float mi = mean[i];
    const float invN = 1.0f / (float)NBL;
    float s = 0.0f;
    for (int j = threadIdx.x; j < DD; j += 256) {
        if (j == i) continue;
        float c = G[(size_t)i * DD + j] * invN - mi * mean[j];
        s += c * c;
    }
    red[threadIdx.x] = s;
    __syncthreads();
    for (int off = 128; off > 0; off >>= 1) {
        if (threadIdx.x < off) red[threadIdx.x] += red[threadIdx.x + off];
        __syncthreads();
    }
    if (threadIdx.x == 0) partial[i] = red[0];
}

__global__ void decov_final(const float* __restrict__ partial, float* __restrict__ out)
{
    __shared__ float red[256];
    float s = 0.0f;
    for (int i = threadIdx.x; i < DD; i += 256) s += partial[i];
    red[threadIdx.x] = s;
    __syncthreads();
    for (int off = 128; off > 0; off >>= 1) {
        if (threadIdx.x < off) red[threadIdx.x] += red[threadIdx.x + off];
        __syncthreads();
    }
    if (threadIdx.x == 0) out[0] = 0.5f * red[0];
}

// ---------------- launch ------------------------------------------------------
extern "C" void kernel_launch(void* const* d_in, const int* in_sizes, int n_in,
                              void* d_out, int out_size)
{
    const float* x  = (const float*)d_in[0];
    const float* Wq = (const float*)d_in[1];
    const float* bq = (const float*)d_in[2];
    const float* Wk = (const float*)d_in[3];
    const float* bk = (const float*)d_in[4];
    const float* Wv = (const float*)d_in[5];
    const float* bv = (const float*)d_in[6];
    const float* Wo = (const float*)d_in[7];
    const float* bo = (const float*)d_in[8];
    float* out = (float*)d_out;

    float *QKVp, *Mp, *Gp, *meanp, *partp, *Opart, *Gpart, *bqkv;
    cudaGetSymbolAddress((void**)&QKVp, g_QKV);
    cudaGetSymbolAddress((void**)&Mp, g_M);
    cudaGetSymbolAddress((void**)&Gp, g_G);
    cudaGetSymbolAddress((void**)&meanp, g_mean);
    cudaGetSymbolAddress((void**)&partp, g_partial);
    cudaGetSymbolAddress((void**)&Opart, g_Opart);
    cudaGetSymbolAddress((void**)&Gpart, g_Gpart);
    cudaGetSymbolAddress((void**)&bqkv, g_bqkv);

    __half *xh, *xl, *Mh, *Ml, *Mth, *Mtl, *Wqkvh, *Woh;
    cudaGetSymbolAddress((void**)&xh, g_xh);
    cudaGetSymbolAddress((void**)&xl, g_xl);
    cudaGetSymbolAddress((void**)&Mh, g_Mh);
    cudaGetSymbolAddress((void**)&Ml, g_Ml);
    cudaGetSymbolAddress((void**)&Mth, g_Mth);
    cudaGetSymbolAddress((void**)&Mtl, g_Mtl);
    cudaGetSymbolAddress((void**)&Wqkvh, g_Wqkvh);
    cudaGetSymbolAddress((void**)&Woh, g_Woh);

    cudaFuncSetAttribute(gemm2, cudaFuncAttributeMaxDynamicSharedMemorySize,
                         GSMEM);

    const int n4x = MTOT * DD / 4;      // 1M float4
    const int n4w = DD * DD / 4;        // 256K float4

    // input splits / weight rounding
    split_fp16<<<n4x / 256, 256>>>(x, xh, xl, n4x);
    round_fp16<<<n4w / 256, 256>>>(Wq, Wqkvh, n4w);
    round_fp16<<<n4w / 256, 256>>>(Wk, Wqkvh + DD * DD, n4w);
    round_fp16<<<n4w / 256, 256>>>(Wv, Wqkvh + 2 * DD * DD, n4w);
    round_fp16<<<n4w / 256, 256>>>(Wo, Woh, n4w);
    cudaMemcpyAsync(bqkv, bq, DD * sizeof(float), cudaMemcpyDeviceToDevice);
    cudaMemcpyAsync(bqkv + DD, bk, DD * sizeof(float), cudaMemcpyDeviceToDevice);
    cudaMemcpyAsync(bqkv + 2 * DD, bv, DD * sizeof(float), cudaMemcpyDeviceToDevice);

    // fused QKV projection: [4096,1024] @ [3072,1024]^T -> [4096,3072]
    dim3 gQKV(3 * DD / 128, MTOT / 128, 1);   // (24, 32)
    gemm2<<<gQKV, 256, GSMEM>>>(xh, xl, Wqkvh, bqkv, QKVp, nullptr,
                                DD, DD, 3 * DD);

    // attention
    dim3 gAttn(LL / 128, HH, BB);
    attn_kernel<<<gAttn, 128>>>(QKVp, Mp);

    // split merged output (row-major + transposed)
    split_fp16<<<n4x / 256, 256>>>(Mp, Mh, Ml, n4x);
    transpose_split_fp16<<<dim3(DD / 32, NBL / 32), dim3(32, 8)>>>(Mp, Mth, Mtl);

    // output projection with split-K=2
    dim3 gOut(DD / 128, MTOT / 128, 2);       // (8, 32, 2)
    gemm2<<<gOut, 256, GSMEM>>>(Mh, Ml, Woh, nullptr, nullptr, Opart,
                                DD, DD / 2, DD);
    reduce_parts<<<(MTOT * DD / 4) / 256, 256>>>(Opart, 2, bo, out,
                                                 MTOT * DD, DD);

    // DeCov path: syrk with split-K=4
    colmean_kernel<<<DD / 256, 256>>>(Mp, meanp);
    dim3 gSyrk(DD / 128, DD / 128, 4);        // (8, 8, 4)
    gemm2<<<gSyrk, 256, GSMEM>>>(Mth, Mtl, Mth, nullptr, nullptr, Gpart,
                                 NBL, NBL / 4, DD);
    reduce_parts<<<(DD * DD / 4) / 256, 256>>>(Gpart, 4, nullptr, Gp,
                                               DD * DD, DD);
    decov_row<<<DD, 256>>>(Gp, meanp, partp);
    decov_final<<<1, 256>>>(partp, out + (out_size - 1));
}